// round 6
// baseline (speedup 1.0000x reference)
#include <cuda_runtime.h>
#include <cuda_bf16.h>
#include <cstdint>

// ---------------------------------------------------------------------------
// GlobalMatchingTokenizer: 3 levels of efficient global matching attention.
// B=2, C={64,128,192}, H=W={64,32,16}, N=H*W, TOKEN_DIM=192, NUM_HEADS=4,
// HEAD_DIM=48, TOPK=128.
// Round 6: scores GEMM on tensor cores via mma.sync with a 3-term bf16
// mantissa split (6 product terms) -> fp32-accuracy scores (top-k safe).
// ---------------------------------------------------------------------------

#define NH 4
#define HD 48
#define TD 192
#define KSEL 128
#define TN 16
#define CAP 256

// Scratch (device globals: allowed; no dynamic allocation anywhere).
__device__ float g_S[134217728];                 // 2*4*4096*4096 floats = 512 MB
__device__ __nv_bfloat16 g_Q1[2 * NH * 4096 * HD];
__device__ __nv_bfloat16 g_Q2[2 * NH * 4096 * HD];
__device__ __nv_bfloat16 g_Q3[2 * NH * 4096 * HD];
__device__ __nv_bfloat16 g_K1[2 * NH * 4096 * HD];
__device__ __nv_bfloat16 g_K2[2 * NH * 4096 * HD];
__device__ __nv_bfloat16 g_K3[2 * NH * 4096 * HD];
__device__ float g_V[2 * NH * 4096 * HD];
__device__ float g_O[2 * NH * 4096 * HD];

__device__ __forceinline__ uint32_t smem_u32(const void* p)
{
    uint32_t a;
    asm("{ .reg .u64 t; cvta.to.shared.u64 t, %1; cvt.u32.u64 %0, t; }"
        : "=r"(a) : "l"(p));
    return a;
}
__device__ __forceinline__ uint32_t swz128(uint32_t off)
{
    return off ^ ((off >> 3) & 0x70u);
}
__device__ __forceinline__ void ldmx4(uint32_t* r, uint32_t addr)
{
    asm volatile("ldmatrix.sync.aligned.m8n8.x4.shared.b16 {%0,%1,%2,%3}, [%4];"
                 : "=r"(r[0]), "=r"(r[1]), "=r"(r[2]), "=r"(r[3]) : "r"(addr));
}
__device__ __forceinline__ void mma16816(float* c, const uint32_t* a,
                                         uint32_t b0, uint32_t b1)
{
    asm volatile("mma.sync.aligned.m16n8k16.row.col.f32.bf16.bf16.f32 "
                 "{%0,%1,%2,%3}, {%4,%5,%6,%7}, {%8,%9}, {%0,%1,%2,%3};"
                 : "+f"(c[0]), "+f"(c[1]), "+f"(c[2]), "+f"(c[3])
                 : "r"(a[0]), "r"(a[1]), "r"(a[2]), "r"(a[3]), "r"(b0), "r"(b1));
}

// ---------------------------------------------------------------------------
// Kernel 1: QKV projection + positional encoding; emits 3-term bf16 split.
// grid = B*(N/TN), 384 threads.
// ---------------------------------------------------------------------------
__global__ void proj_kernel(const float* __restrict__ f1,
                            const float* __restrict__ f2,
                            const float* __restrict__ qw, const float* __restrict__ qb,
                            const float* __restrict__ kw, const float* __restrict__ kb,
                            const float* __restrict__ vw, const float* __restrict__ vb,
                            int C, int N, int W)
{
    __shared__ float s1[TD][TN];
    __shared__ float s2[TD][TN];
    const int tid  = threadIdx.x;
    const int t    = tid % TD;
    const int half = tid / TD;
    const int nt = N / TN;
    const int n0 = (blockIdx.x % nt) * TN;
    const int b  = blockIdx.x / nt;

    for (int i = tid; i < C * TN; i += 384) {
        const int c = i / TN, j = i % TN;
        s1[c][j] = f1[((size_t)b * C + c) * N + n0 + j];
        s2[c][j] = f2[((size_t)b * C + c) * N + n0 + j];
    }
    __syncthreads();

    const int j0 = half * (TN / 2);
    float aq[TN / 2], ak[TN / 2], av[TN / 2];
    const float bq = qb[t], bk = kb[t], bv = vb[t];
    #pragma unroll
    for (int j = 0; j < TN / 2; ++j) { aq[j] = bq; ak[j] = bk; av[j] = bv; }

    for (int c = 0; c < C; ++c) {
        const float wq = qw[c * TD + t];
        const float wk = kw[c * TD + t];
        const float wv = vw[c * TD + t];
        #pragma unroll
        for (int j = 0; j < TN / 2; ++j) {
            const float a1 = s1[c][j0 + j];
            const float a2 = s2[c][j0 + j];
            aq[j] = fmaf(a1, wq, aq[j]);
            ak[j] = fmaf(a2, wk, ak[j]);
            av[j] = fmaf(a2, wv, av[j]);
        }
    }

    const float step = -9.210340371976184f / 96.0f;  // -ln(10000)/96
    const float div  = expf(step * (float)(t < 96 ? t : t - 96));
    #pragma unroll
    for (int j = 0; j < TN / 2; ++j) {
        const int n = n0 + j0 + j;
        const float pe = (t < 96) ? sinf((float)(n % W) * div)
                                  : cosf((float)(n / W) * div);
        aq[j] += pe;
        ak[j] += pe;
    }

    const int h = t / HD;
    const int d = t % HD;
    const size_t base = (((size_t)b * NH + h) * N + n0 + j0) * HD + d;
    #pragma unroll
    for (int j = 0; j < TN / 2; ++j) {
        const size_t idx = base + (size_t)j * HD;
        // 3-term bf16 mantissa split of q and k.
        float r = aq[j];
        __nv_bfloat16 t1 = __float2bfloat16(r);
        g_Q1[idx] = t1;
        r -= __bfloat162float(t1);
        __nv_bfloat16 t2 = __float2bfloat16(r);
        g_Q2[idx] = t2;
        r -= __bfloat162float(t2);
        g_Q3[idx] = __float2bfloat16(r);

        r = ak[j];
        t1 = __float2bfloat16(r);
        g_K1[idx] = t1;
        r -= __bfloat162float(t1);
        t2 = __float2bfloat16(r);
        g_K2[idx] = t2;
        r -= __bfloat162float(t2);
        g_K3[idx] = __float2bfloat16(r);

        g_V[idx] = av[j];
    }
}

// ---------------------------------------------------------------------------
// Kernel 2: scores GEMM via mma.sync (HMMA bf16, fp32 accum), 6 split terms:
// S ~= scale * (Q1K1 + Q1K2 + Q2K1 + Q1K3 + Q2K2 + Q3K1)  (error ~ fp32 ulp).
// One 128x128 S-tile per CTA. 8 warps, warp tile m64 x n32.
// SMEM: 6 bf16 tiles 128x64(pad), SW128-swizzled, row-major [row][k].
// ---------------------------------------------------------------------------
#define SC_TILE_B 16384u                 // 128 rows * 128 bytes
#define SC_SMEM   (6u * SC_TILE_B)       // 96 KB dynamic smem

__global__ void __launch_bounds__(256) scores_kernel(int N)
{
    extern __shared__ char smem[];
    const uint32_t sb = smem_u32(smem);
    const int tid = threadIdx.x;
    const int wid = tid >> 5, lane = tid & 31;
    const int bh = blockIdx.z;
    const int rb = blockIdx.y * 128;
    const int cb = blockIdx.x * 128;

    // Load 6 tiles: Q1..Q3 (rows rb..), K1..K3 (rows cb..).
    const size_t qoff = ((size_t)bh * N + rb) * HD;
    const size_t koff = ((size_t)bh * N + cb) * HD;
    const __nv_bfloat16* srcs[6] = { g_Q1 + qoff, g_Q2 + qoff, g_Q3 + qoff,
                                     g_K1 + koff, g_K2 + koff, g_K3 + koff };
    #pragma unroll
    for (int a = 0; a < 6; ++a) {
        const __nv_bfloat16* src = srcs[a];
        char* dst = smem + a * SC_TILE_B;
        for (int i = tid; i < 128 * 12; i += 256) {
            const int r = i / 12, c4 = i % 12;
            const uint2 v = *(const uint2*)(src + (size_t)r * HD + c4 * 4);
            *(uint2*)(dst + swz128((uint32_t)(r * 128 + c4 * 8))) = v;
        }
    }
    __syncthreads();

    const int warp_m = wid & 1;          // m offset 64*warp_m
    const int warp_n = wid >> 1;         // n offset 32*warp_n

    float acc[4][4][4] = {};             // [m-atom][n-atom][frag]

    const int lrow = lane & 15;
    const int lcol = (lane >> 4) << 4;

    // Split product terms (Q index, K index), magnitudes >= 2^-18.
    const int tA[6] = {0, 0, 1, 0, 1, 2};
    const int tB[6] = {0, 1, 0, 2, 1, 0};

    #pragma unroll
    for (int term = 0; term < 6; ++term) {
        const uint32_t abase = sb + (uint32_t)tA[term] * SC_TILE_B;
        const uint32_t bbase = sb + (3u + (uint32_t)tB[term]) * SC_TILE_B;
        #pragma unroll
        for (int ks = 0; ks < 3; ++ks) {
            const int k0b = ks * 32;     // 16 bf16 = 32 bytes

            uint32_t afrag[4][4];
            #pragma unroll
            for (int mi = 0; mi < 4; ++mi) {
                const int row = warp_m * 64 + mi * 16 + lrow;
                ldmx4(afrag[mi], abase + swz128((uint32_t)(row * 128 + k0b + lcol)));
            }
            uint32_t bfrag[2][4];        // each x4 covers two n8 atoms
            #pragma unroll
            for (int nj = 0; nj < 2; ++nj) {
                const int row = warp_n * 32 + nj * 16 + lrow;
                ldmx4(bfrag[nj], bbase + swz128((uint32_t)(row * 128 + k0b + lcol)));
            }
            #pragma unroll
            for (int mi = 0; mi < 4; ++mi)
                #pragma unroll
                for (int ni = 0; ni < 4; ++ni)
                    mma16816(acc[mi][ni], afrag[mi],
                             bfrag[ni >> 1][ni & 1], bfrag[ni >> 1][(ni & 1) + 2]);
        }
    }

    // Epilogue: scale + direct store.
    const float scale = 0.14433756729740643f;  // 1/sqrt(48)
    float* __restrict__ Sb = g_S + (size_t)bh * N * N;
    const int r0 = rb + warp_m * 64 + (lane >> 2);
    const int c0 = cb + warp_n * 32 + (lane & 3) * 2;
    #pragma unroll
    for (int mi = 0; mi < 4; ++mi) {
        #pragma unroll
        for (int ni = 0; ni < 4; ++ni) {
            const int r = r0 + mi * 16;
            const int c = c0 + ni * 8;
            *(float2*)&Sb[(size_t)r * N + c] =
                make_float2(acc[mi][ni][0] * scale, acc[mi][ni][1] * scale);
            *(float2*)&Sb[(size_t)(r + 8) * N + c] =
                make_float2(acc[mi][ni][2] * scale, acc[mi][ni][3] * scale);
        }
    }
}

// ---------------------------------------------------------------------------
// Kernel 3: exact top-128 (radix select, parallel bucket pick) + softmax + AV.
// ---------------------------------------------------------------------------
__device__ __forceinline__ unsigned int floatToKey(float f)
{
    unsigned int u = __float_as_uint(f);
    return (u & 0x80000000u) ? ~u : (u | 0x80000000u);
}
__device__ __forceinline__ float keyToFloat(unsigned int u)
{
    unsigned int b = (u & 0x80000000u) ? (u & 0x7fffffffu) : ~u;
    return __uint_as_float(b);
}

__global__ void attn_kernel(int N)
{
    extern __shared__ unsigned int keys[];
    __shared__ unsigned int hist[256];
    __shared__ unsigned int ckey[CAP];
    __shared__ int          cidx[CAP];
    __shared__ float        wl[KSEL];
    __shared__ int          ml[KSEL];
    __shared__ float        accs[HD];
    __shared__ int          wsum[8];
    __shared__ int          wsuf[9];
    __shared__ unsigned int s_prefix, s_maxkey;
    __shared__ int          s_need, s_cand, s_cnt, s_ccnt;
    __shared__ float        s_Z;

    const int tid = threadIdx.x;
    const size_t row = blockIdx.x;
    const float* __restrict__ Srow = g_S + row * (size_t)N;

    if (tid == 0) {
        s_maxkey = 0u; s_cnt = 0; s_ccnt = 0; s_Z = 0.f;
        s_prefix = 0u; s_need = KSEL;
    }
    if (tid < HD) accs[tid] = 0.f;
    hist[tid] = 0u;
    __syncthreads();

    unsigned int lmax = 0u;
    for (int m = tid; m < N; m += 256) {
        const unsigned int u = floatToKey(Srow[m]);
        keys[m] = u;
        lmax = max(lmax, u);
        atomicAdd(&hist[u >> 24], 1u);
    }
    #pragma unroll
    for (int off = 16; off; off >>= 1)
        lmax = max(lmax, __shfl_down_sync(0xffffffffu, lmax, off));
    if ((tid & 31) == 0) atomicMax(&s_maxkey, lmax);
    __syncthreads();

    int p = 0;
    for (;;) {
        const int need = s_need;
        const int h = (int)hist[tid];
        int x = h;
        #pragma unroll
        for (int off = 1; off < 32; off <<= 1) {
            const int y = __shfl_down_sync(0xffffffffu, x, off);
            if ((tid & 31) + off < 32) x += y;
        }
        if ((tid & 31) == 0) wsum[tid >> 5] = x;
        __syncthreads();
        if (tid == 0) {
            int s = 0;
            for (int w = 7; w >= 0; --w) { s += wsum[w]; wsuf[w] = s; }
            wsuf[8] = 0;
        }
        __syncthreads();
        const int suffix  = x + wsuf[(tid >> 5) + 1];
        const int sufNext = suffix - h;
        if (suffix >= need && sufNext < need) {
            s_need   = need - sufNext;
            s_cand   = h;
            s_prefix = (s_prefix << 8) | (unsigned int)tid;
        }
        __syncthreads();
        if (s_cand <= CAP || p == 3) break;

        hist[tid] = 0u;
        __syncthreads();
        const unsigned int pfx = s_prefix;
        const int shift = 24 - 8 * p, nshift = shift - 8;
        for (int m = tid; m < N; m += 256) {
            const unsigned int u = keys[m];
            if ((u >> shift) == pfx)
                atomicAdd(&hist[(u >> nshift) & 255u], 1u);
        }
        __syncthreads();
        ++p;
    }

    const int shift = 24 - 8 * p;
    const unsigned int P = s_prefix;
    const int needC = s_need;
    const bool capok = (s_cand <= CAP);
    const float smax = keyToFloat(s_maxkey);

    for (int m = tid; m < N; m += 256) {
        const unsigned int u = keys[m];
        const unsigned int ub = u >> shift;
        if (ub > P) {
            const int slot = atomicAdd(&s_cnt, 1);
            if (slot < KSEL) {
                wl[slot] = __expf(keyToFloat(u) - smax);
                ml[slot] = m;
            }
        } else if (ub == P && capok) {
            const int slot = atomicAdd(&s_ccnt, 1);
            if (slot < CAP) { ckey[slot] = u; cidx[slot] = m; }
        }
    }
    __syncthreads();

    if (capok) {
        const int c = min(s_ccnt, CAP);
        for (int i = tid; i < c; i += 256) {
            const unsigned int ki = ckey[i];
            const int idi = cidx[i];
            int r = 0;
            for (int j = 0; j < c; ++j) {
                const unsigned int kj = ckey[j];
                r += (kj > ki) || (kj == ki && cidx[j] < idi);
            }
            if (r < needC) {
                const int slot = atomicAdd(&s_cnt, 1);
                if (slot < KSEL) {
                    wl[slot] = __expf(keyToFloat(ki) - smax);
                    ml[slot] = idi;
                }
            }
        }
    } else {
        for (int m = tid; m < N; m += 256) {
            const unsigned int u = keys[m];
            if (u == P) {
                int r = 0;
                for (int j = 0; j < m; ++j) r += (keys[j] == P);
                if (r < needC) {
                    const int slot = atomicAdd(&s_cnt, 1);
                    if (slot < KSEL) {
                        wl[slot] = __expf(keyToFloat(u) - smax);
                        ml[slot] = m;
                    }
                }
            }
        }
    }
    __syncthreads();

    const int total = min(s_cnt, KSEL);

    float z = (tid < total) ? wl[tid] : 0.f;
    #pragma unroll
    for (int off = 16; off; off >>= 1)
        z += __shfl_down_sync(0xffffffffu, z, off);
    if ((tid & 31) == 0) atomicAdd(&s_Z, z);
    __syncthreads();

    const size_t bh = row / (size_t)N;
    const float* __restrict__ Vb = g_V + bh * (size_t)N * HD;

    if (tid < 192) {
        const int d = tid % HD;
        const int ch = tid / HD;
        float a = 0.f;
        #pragma unroll 4
        for (int i = ch; i < total; i += 4)
            a = fmaf(wl[i], __ldg(&Vb[(size_t)ml[i] * HD + d]), a);
        atomicAdd(&accs[d], a);
    }
    __syncthreads();

    if (tid < HD)
        g_O[row * HD + tid] = accs[tid] / s_Z;
}

// ---------------------------------------------------------------------------
// Kernel 4: output projection, n-tiled, 384 threads.
// ---------------------------------------------------------------------------
__global__ void oproj_kernel(const float* __restrict__ ow,
                             const float* __restrict__ ob,
                             float* __restrict__ out, int N)
{
    __shared__ float o[TD][TN + 1];
    const int tid  = threadIdx.x;
    const int t    = tid % TD;
    const int half = tid / TD;
    const int nt = N / TN;
    const int n0 = (blockIdx.x % nt) * TN;
    const int b  = blockIdx.x / nt;

    for (int i = tid; i < TD * TN; i += 384) {
        const int j  = i / TD;
        const int td = i % TD;
        const int h = td / HD, d = td % HD;
        o[td][j] = g_O[(((size_t)b * NH + h) * N + n0 + j) * HD + d];
    }
    __syncthreads();

    const int j0 = half * (TN / 2);
    float acc[TN / 2];
    const float bias = ob[t];
    #pragma unroll
    for (int j = 0; j < TN / 2; ++j) acc[j] = bias;

    for (int j = 0; j < TD; ++j) {
        const float w = ow[j * TD + t];
        #pragma unroll
        for (int jj = 0; jj < TN / 2; ++jj)
            acc[jj] = fmaf(o[j][j0 + jj], w, acc[jj]);
    }

    float4* op = (float4*)(out + ((size_t)b * TD + t) * N + n0 + j0);
    #pragma unroll
    for (int q = 0; q < TN / 8; ++q)
        op[q] = make_float4(acc[4 * q], acc[4 * q + 1], acc[4 * q + 2], acc[4 * q + 3]);
}

// ---------------------------------------------------------------------------
// Launch: 3 levels sequentially.
// ---------------------------------------------------------------------------
extern "C" void kernel_launch(void* const* d_in, const int* in_sizes, int n_in,
                              void* d_out, int out_size)
{
    (void)in_sizes; (void)n_in; (void)out_size;

    cudaFuncSetAttribute(scores_kernel,
                         cudaFuncAttributeMaxDynamicSharedMemorySize, SC_SMEM);

    const int Cs[3] = {64, 128, 192};
    const int Hs[3] = {64, 32, 16};

    size_t out_off = 0;
    for (int l = 0; l < 3; ++l) {
        const int C = Cs[l];
        const int H = Hs[l];
        const int N = H * H;
        const int B = 2;

        const float* f1 = (const float*)d_in[2 * l + 0];
        const float* f2 = (const float*)d_in[2 * l + 1];
        const int wb = 6 + 8 * l;
        const float* qw = (const float*)d_in[wb + 0];
        const float* qb = (const float*)d_in[wb + 1];
        const float* kw = (const float*)d_in[wb + 2];
        const float* kb = (const float*)d_in[wb + 3];
        const float* vw = (const float*)d_in[wb + 4];
        const float* vb = (const float*)d_in[wb + 5];
        const float* ow = (const float*)d_in[wb + 6];
        const float* ob = (const float*)d_in[wb + 7];

        float* outp = (float*)d_out + out_off;

        proj_kernel<<<B * (N / TN), 384>>>(f1, f2, qw, qb, kw, kb, vw, vb, C, N, H);

        dim3 sg(N / 128, N / 128, B * NH);
        scores_kernel<<<sg, 256, SC_SMEM>>>(N);

        attn_kernel<<<B * NH * N, 256, (size_t)N * sizeof(unsigned int)>>>(N);

        oproj_kernel<<<B * (N / TN), 384>>>(ow, ob, outp, N);

        out_off += (size_t)B * TD * N;
    }
}